// round 15
// baseline (speedup 1.0000x reference)
#include <cuda_runtime.h>
#include <cuda_bf16.h>
#include <math.h>
#include <stdint.h>

#define Bn   4096
#define Dd   112
#define NTd  200
#define Hh   512
#define HIDd 512
#define CN   536
#define G3   1536
#define TOTR (Dd*Bn)
#define NCTA 128

// ---------------- device scratch ---------------------------------------------
__device__ float g_const[(size_t)Bn * CN];
__device__ float g_gic  [(size_t)Bn * G3];
__device__ float4 g_gic4[(size_t)Bn * Hh];
__device__ float4 g_wz4 [Hh];
__device__ float g_mlpc [(size_t)Bn * HIDd];
__device__ float g_Hf   [2 * (size_t)Bn * Hh];
__device__ __nv_bfloat16 g_Hbf [(size_t)(Dd+1) * Bn * Hh];
__device__ __nv_bfloat16 g_WhhT[(size_t)G3 * Hh];
__device__ __nv_bfloat16 g_W0T [(size_t)HIDd * Hh];
__device__ __nv_bfloat16 g_W1T [(size_t)HIDd * HIDd];
__device__ __nv_bfloat16 g_W2T [(size_t)32 * 512];
__device__ __nv_bfloat16 g_A1bf[(size_t)TOTR * HIDd];
__device__ float g_ll   [(size_t)Dd * Bn];           // [t][b]
__device__ unsigned g_bar_cnt2 [16];
__device__ unsigned g_bar_flag2[16];

// ---------------- helpers ----------------------------------------------------
__device__ __forceinline__ float fast_sig(float x)  { return 1.f / (1.f + __expf(-x)); }
__device__ __forceinline__ float fast_tanh(float x) { return fmaf(2.f, 1.f / (1.f + __expf(-2.f * x)), -1.f); }

__device__ __forceinline__ uint32_t pack_bf16x2(float lo, float hi)
{
    uint32_t r;
    asm("cvt.rn.bf16x2.f32 %0, %1, %2;" : "=r"(r) : "f"(hi), "f"(lo));
    return r;
}
__device__ __forceinline__ uint32_t smem_u32(const void* p)
{
    uint32_t a;
    asm("{ .reg .u64 t; cvta.to.shared.u64 t, %1; cvt.u32.u64 %0, t; }" : "=r"(a) : "l"(p));
    return a;
}
__device__ __forceinline__ void cpa16_u(uint32_t dst, const void* src)
{
    asm volatile("cp.async.cg.shared.global [%0], [%1], 16;\n" :: "r"(dst), "l"(src));
}
__device__ __forceinline__ void cpa8_u(uint32_t dst, const void* src)
{
    asm volatile("cp.async.ca.shared.global [%0], [%1], 8;\n" :: "r"(dst), "l"(src));
}
__device__ __forceinline__ void cpa_commit() { asm volatile("cp.async.commit_group;\n"); }
template<int N>
__device__ __forceinline__ void cpa_wait()   { asm volatile("cp.async.wait_group %0;\n" :: "n"(N)); }

__device__ __forceinline__ uint32_t f2tf32(float x)
{
    uint32_t u;
    asm("cvt.rna.tf32.f32 %0, %1;" : "=r"(u) : "f"(x));
    return u;
}
__device__ __forceinline__ void mma_tf32(float* d, const uint32_t* a, const uint32_t* b)
{
    asm volatile(
        "mma.sync.aligned.m16n8k8.row.col.f32.tf32.tf32.f32 "
        "{%0,%1,%2,%3}, {%4,%5,%6,%7}, {%8,%9}, {%0,%1,%2,%3};\n"
        : "+f"(d[0]), "+f"(d[1]), "+f"(d[2]), "+f"(d[3])
        : "r"(a[0]), "r"(a[1]), "r"(a[2]), "r"(a[3]), "r"(b[0]), "r"(b[1]));
}
__device__ __forceinline__ void mma_bf16(float* d, const uint32_t* a, const uint32_t* b)
{
    asm volatile(
        "mma.sync.aligned.m16n8k16.row.col.f32.bf16.bf16.f32 "
        "{%0,%1,%2,%3}, {%4,%5,%6,%7}, {%8,%9}, {%0,%1,%2,%3};\n"
        : "+f"(d[0]), "+f"(d[1]), "+f"(d[2]), "+f"(d[3])
        : "r"(a[0]), "r"(a[1]), "r"(a[2]), "r"(a[3]), "r"(b[0]), "r"(b[1]));
}

// ---------------- merged prep kernel -----------------------------------------
__global__ void prep_kernel(const float* __restrict__ c,
                            const float* __restrict__ bb,
                            const float* __restrict__ m,
                            const float* __restrict__ Wih)
{
    size_t idx = (size_t)blockIdx.x * blockDim.x + threadIdx.x;
    const size_t R1 = (size_t)Bn * CN;
    const size_t R2 = R1 + (size_t)Bn * Hh;
    if (idx < R1) {
        int b = (int)(idx / CN);
        int i = (int)(idx % CN);
        float v;
        if (i < Dd + NTd)            v = c [(size_t)b * (Dd + NTd) + i];
        else if (i < Dd + NTd + Dd)  v = bb[(size_t)b * Dd + (i - (Dd + NTd))];
        else                         v = m [(size_t)b * Dd + (i - (Dd + NTd + Dd))];
        g_const[idx] = v;
    } else if (idx < R2) {
        size_t i2 = idx - R1;
        g_Hf[i2] = 0.f;
        g_Hbf[i2] = __float2bfloat16(0.f);
    } else if (idx < R2 + Hh) {
        int j = (int)(idx - R2);
        g_wz4[j] = make_float4(Wih[j], Wih[512 + j], Wih[1024 + j], 0.f);
        if (j < 16) { g_bar_cnt2[j] = 0; g_bar_flag2[j] = 0; }
    }
}

__global__ void gic4_pack_kernel(const float* __restrict__ bhh)
{
    size_t idx = (size_t)blockIdx.x * blockDim.x + threadIdx.x;
    if (idx >= (size_t)Bn * Hh) return;
    int b = (int)(idx >> 9);
    int j = (int)(idx & 511);
    const float* g = g_gic + (size_t)b * G3;
    g_gic4[idx] = make_float4(g[j] + bhh[j],
                              g[512 + j] + bhh[512 + j],
                              g[1024 + j],
                              bhh[1024 + j]);
}

__global__ void convT3_kernel(const float* __restrict__ Whh,
                              const float* __restrict__ W0,
                              const float* __restrict__ W1)
{
    __shared__ float tile[32][33];
    const float* in;
    __nv_bfloat16* out;
    int Krows = 512, Ncols;
    if (blockIdx.z == 0)      { in = Whh; out = g_WhhT; Ncols = G3; }
    else if (blockIdx.z == 1) { in = W0;  out = g_W0T;  Ncols = HIDd; }
    else                      { in = W1;  out = g_W1T;  Ncols = HIDd; }
    int n0 = blockIdx.x * 32;
    if (n0 >= Ncols) return;
    int k0 = blockIdx.y * 32;
    int tx = threadIdx.x, ty = threadIdx.y;
    for (int i = ty; i < 32; i += 8)
        tile[i][tx] = in[(size_t)(k0 + i) * Ncols + n0 + tx];
    __syncthreads();
    for (int i = ty; i < 32; i += 8)
        out[(size_t)(n0 + i) * Krows + k0 + tx] = __float2bfloat16(tile[tx][i]);
}

__global__ void w2t_kernel(const float* __restrict__ W2)
{
    int idx = blockIdx.x * 256 + threadIdx.x;
    if (idx >= 32 * 512) return;
    int n = idx >> 9, k = idx & 511;
    g_W2T[idx] = (n < 30) ? __float2bfloat16(W2[k * 30 + n]) : __float2bfloat16(0.f);
}

// ---------------- tf32 GEMM for K=536 precompute -----------------------------
__global__ __launch_bounds__(256)
void tgemm_kernel(const float* __restrict__ A, const float* __restrict__ B,
                  const float* __restrict__ bias, float* __restrict__ C,
                  int M, int N, int K)
{
    __shared__ uint32_t As[128][12];
    __shared__ uint32_t Bs[8][136];

    const int tid  = threadIdx.x;
    const int wid  = tid >> 5;
    const int lane = tid & 31;
    const int gid  = lane >> 2;
    const int tig  = lane & 3;
    const int wm   = wid >> 2;
    const int wn   = wid & 3;
    const int row0 = blockIdx.y * 128;
    const int col0 = blockIdx.x * 128;

    float acc[4][4][4];
#pragma unroll
    for (int mt = 0; mt < 4; mt++)
#pragma unroll
        for (int nt = 0; nt < 4; nt++)
#pragma unroll
            for (int r = 0; r < 4; r++) acc[mt][nt][r] = 0.f;

    const int ar = tid >> 1;
    const int ak = (tid & 1) * 4;
    const int bk = tid >> 5;
    const int bn = (tid & 31) * 4;
    const int niter = K >> 3;

    const float* Ag = A + (size_t)(row0 + ar) * K + ak;
    const float* Bg = B + (size_t)bk * N + col0 + bn;

    float4 pa = *(const float4*)Ag;
    float4 pb = *(const float4*)Bg;

    for (int it = 0; it < niter; ++it) {
        As[ar][ak + 0] = f2tf32(pa.x); As[ar][ak + 1] = f2tf32(pa.y);
        As[ar][ak + 2] = f2tf32(pa.z); As[ar][ak + 3] = f2tf32(pa.w);
        Bs[bk][bn + 0] = f2tf32(pb.x); Bs[bk][bn + 1] = f2tf32(pb.y);
        Bs[bk][bn + 2] = f2tf32(pb.z); Bs[bk][bn + 3] = f2tf32(pb.w);
        __syncthreads();
        if (it + 1 < niter) {
            pa = *(const float4*)(Ag + (size_t)(it + 1) * 8);
            pb = *(const float4*)(Bg + (size_t)(it + 1) * 8 * N);
        }
        uint32_t af[4][4];
#pragma unroll
        for (int mt = 0; mt < 4; mt++) {
            int rb = wm * 64 + mt * 16 + gid;
            af[mt][0] = As[rb][tig];     af[mt][1] = As[rb + 8][tig];
            af[mt][2] = As[rb][tig + 4]; af[mt][3] = As[rb + 8][tig + 4];
        }
        uint32_t bf[4][2];
#pragma unroll
        for (int nt = 0; nt < 4; nt++) {
            int cb = wn * 32 + nt * 8 + gid;
            bf[nt][0] = Bs[tig][cb]; bf[nt][1] = Bs[tig + 4][cb];
        }
#pragma unroll
        for (int mt = 0; mt < 4; mt++)
#pragma unroll
            for (int nt = 0; nt < 4; nt++)
                mma_tf32(acc[mt][nt], af[mt], bf[nt]);
        __syncthreads();
    }
#pragma unroll
    for (int mt = 0; mt < 4; mt++) {
        int row_lo = row0 + wm * 64 + mt * 16 + gid;
        int row_hi = row_lo + 8;
#pragma unroll
        for (int nt = 0; nt < 4; nt++) {
            int col = col0 + wn * 32 + nt * 8 + tig * 2;
            float b0 = bias[col], b1 = bias[col + 1];
            *(float2*)(C + (size_t)row_lo * N + col) =
                make_float2(acc[mt][nt][0] + b0, acc[mt][nt][1] + b1);
            *(float2*)(C + (size_t)row_hi * N + col) =
                make_float2(acc[mt][nt][2] + b0, acc[mt][nt][3] + b1);
        }
    }
}

// ============ PERSISTENT weight-stationary GRU recurrence (1024 thr) =========
__global__ __launch_bounds__(1024, 1)
void gru_persist(const __nv_bfloat16* __restrict__ Hbf,
                 float* __restrict__ Hf,
                 const __nv_bfloat16* __restrict__ WhhT,
                 const float* __restrict__ z)
{
    extern __shared__ uint32_t sm[];
    const int tid  = threadIdx.x;
    const int wid  = tid >> 5;
    const int lane = tid & 31;
    const int gid  = lane >> 2;
    const int t4   = lane & 3;
    const int wm   = wid >> 2;
    const int wn   = wid & 3;
    const int jb   = blockIdx.x & 7;
    const int mb   = blockIdx.x >> 3;
    uint32_t su = smem_u32(sm);
    const uint32_t BW = 7680;

    for (int i = tid; i < 12288; i += 1024) {
        int n_row = i >> 6;
        int c16   = i & 63;
        int g = n_row >> 6, n = n_row & 63;
        cpa16_u(su + (BW + (uint32_t)n_row * 260u + (uint32_t)c16 * 4u) * 4u,
                WhhT + ((size_t)(g * 512 + jb * 64 + n)) * 512 + c16 * 8);
    }
    cpa_commit(); cpa_wait<0>(); __syncthreads();

    const int ar  = tid >> 3;
    const int ac4 = (tid & 7) << 1;

#define LOADA(s, kc)                                                            \
    do {                                                                        \
        cpa8_u(su + ((uint32_t)(s) * 2560u + (uint32_t)ar * 20u + ac4) * 4u,    \
               Ag + (size_t)ar * 512 + (kc) * 32 + ac4 * 2);                    \
        cpa_commit();                                                           \
    } while (0)

    for (int t = 0; t < Dd; t++) {
        const __nv_bfloat16* Abase = Hbf + (size_t)t * Bn * Hh + (size_t)mb * 256 * 512;
        const float* Hfp = Hf + (size_t)(t & 1) * Bn * Hh;
        float* Hfn       = Hf + (size_t)((t + 1) & 1) * Bn * Hh;
        __nv_bfloat16* Hbn = (__nv_bfloat16*)(Hbf + (size_t)(t + 1) * Bn * Hh);

        for (int mh = 0; mh < 2; mh++) {
            const __nv_bfloat16* Ag = Abase + (size_t)mh * 128 * 512;

            float acc[3][2][4];
#pragma unroll
            for (int g = 0; g < 3; g++)
#pragma unroll
                for (int nt = 0; nt < 2; nt++)
#pragma unroll
                    for (int r = 0; r < 4; r++) acc[g][nt][r] = 0.f;

            LOADA(0, 0);
            LOADA(1, 1);

            for (int kc = 0; kc < 16; kc++) {
                const int s = kc % 3;
                if (kc < 14) cpa_wait<1>(); else cpa_wait<0>();
                __syncthreads();
                if (kc + 2 < 16) LOADA((kc + 2) % 3, kc + 2);

#pragma unroll
                for (int kb = 0; kb < 16; kb += 8) {
                    uint32_t af[4];
                    {
                        uint32_t base = (uint32_t)s * 2560u + (uint32_t)(wm * 16 + gid) * 20u + kb + t4;
                        af[0] = sm[base];       af[1] = sm[base + 160];
                        af[2] = sm[base + 4];   af[3] = sm[base + 164];
                    }
#pragma unroll
                    for (int g = 0; g < 3; g++)
#pragma unroll
                        for (int nt = 0; nt < 2; nt++) {
                            int nrow = g * 64 + wn * 16 + nt * 8 + gid;
                            uint32_t bbase = BW + (uint32_t)nrow * 260u + (uint32_t)kc * 16u + kb + t4;
                            uint32_t bf[2];
                            bf[0] = sm[bbase];
                            bf[1] = sm[bbase + 4];
                            mma_bf16(acc[g][nt], af, bf);
                        }
                }
            }

            {
                int b_lo = mb * 256 + mh * 128 + wm * 16 + gid;
                int b_hi = b_lo + 8;
                float zt_lo = (t == 0) ? -1.0f : z[(size_t)b_lo * Dd + (t - 1)];
                float zt_hi = (t == 0) ? -1.0f : z[(size_t)b_hi * Dd + (t - 1)];
                const float4* g4lo = g_gic4 + (size_t)b_lo * Hh;
                const float4* g4hi = g_gic4 + (size_t)b_hi * Hh;
                const float* hp_lo = Hfp + (size_t)b_lo * Hh;
                const float* hp_hi = Hfp + (size_t)b_hi * Hh;
                float* hf_lo = Hfn + (size_t)b_lo * Hh;
                float* hf_hi = Hfn + (size_t)b_hi * Hh;
                __nv_bfloat16* hb_lo = Hbn + (size_t)b_lo * Hh;
                __nv_bfloat16* hb_hi = Hbn + (size_t)b_hi * Hh;

#pragma unroll
                for (int nt = 0; nt < 2; nt++) {
                    int jc = jb * 64 + wn * 16 + nt * 8 + t4 * 2;
                    float hlo[2], hhi[2];
#pragma unroll
                    for (int cc = 0; cc < 2; cc++) {
                        int j = jc + cc;
                        float4 w4  = g_wz4[j];
                        float4 glo = g4lo[j];
                        float4 ghi = g4hi[j];
                        {
                            float r = fast_sig(fmaf(zt_lo, w4.x, glo.x) + acc[0][nt][cc]);
                            float u = fast_sig(fmaf(zt_lo, w4.y, glo.y) + acc[1][nt][cc]);
                            float n = fast_tanh(fmaf(r, acc[2][nt][cc] + glo.w,
                                                     fmaf(zt_lo, w4.z, glo.z)));
                            hlo[cc] = fmaf(u, hp_lo[j] - n, n);
                        }
                        {
                            float r = fast_sig(fmaf(zt_hi, w4.x, ghi.x) + acc[0][nt][2 + cc]);
                            float u = fast_sig(fmaf(zt_hi, w4.y, ghi.y) + acc[1][nt][2 + cc]);
                            float n = fast_tanh(fmaf(r, acc[2][nt][2 + cc] + ghi.w,
                                                     fmaf(zt_hi, w4.z, ghi.z)));
                            hhi[cc] = fmaf(u, hp_hi[j] - n, n);
                        }
                    }
                    *(float2*)(hf_lo + jc) = make_float2(hlo[0], hlo[1]);
                    *(float2*)(hf_hi + jc) = make_float2(hhi[0], hhi[1]);
                    *(uint32_t*)(hb_lo + jc) = pack_bf16x2(hlo[0], hlo[1]);
                    *(uint32_t*)(hb_hi + jc) = pack_bf16x2(hhi[0], hhi[1]);
                }
            }
            __syncthreads();
        }

        __threadfence();
        __syncthreads();
        if (tid == 0) {
            unsigned v = atomicAdd(&g_bar_cnt2[mb], 1u);
            if (v == 7u) {
                g_bar_cnt2[mb] = 0;
                __threadfence();
                atomicExch(&g_bar_flag2[mb], (unsigned)(t + 1));
            } else {
                while (atomicAdd(&g_bar_flag2[mb], 0u) < (unsigned)(t + 1)) { }
            }
        }
        __syncthreads();
    }
#undef LOADA
}

// ============ bf16 MLP GEMM layer 1 (tanh + mlpc row bias), bf16 out =========
__global__ __launch_bounds__(256)
void bgemm_mlp(const __nv_bfloat16* __restrict__ A, const __nv_bfloat16* __restrict__ BT,
               const float* __restrict__ bias, __nv_bfloat16* __restrict__ Cout, int M)
{
    const int K = 512, N = 512;
    __shared__ uint32_t As[2][128][20];
    __shared__ uint32_t Bs[2][128][20];

    const int tid  = threadIdx.x;
    const int wid  = tid >> 5;
    const int lane = tid & 31;
    const int g    = lane >> 2;
    const int t    = lane & 3;
    const int wm   = wid >> 2;
    const int wn   = wid & 3;

    const int row0 = blockIdx.y * 128;
    const int col0 = blockIdx.x * 128;

    float acc[4][4][4];
#pragma unroll
    for (int mt = 0; mt < 4; mt++)
#pragma unroll
        for (int nt = 0; nt < 4; nt++)
#pragma unroll
            for (int r = 0; r < 4; r++) acc[mt][nt][r] = 0.f;

    const int lr = tid >> 1;
    const int lc = (tid & 1) * 2;

#define LOAD_STAGE(s, kt)                                                        \
    do {                                                                         \
        cpa16_u(smem_u32(&As[s][lr][lc * 4]),                                    \
                A  + (size_t)(row0 + lr) * K + (kt) * 32 + lc * 8);              \
        cpa16_u(smem_u32(&As[s][lr][(lc + 1) * 4]),                              \
                A  + (size_t)(row0 + lr) * K + (kt) * 32 + (lc + 1) * 8);        \
        cpa16_u(smem_u32(&Bs[s][lr][lc * 4]),                                    \
                BT + (size_t)(col0 + lr) * K + (kt) * 32 + lc * 8);              \
        cpa16_u(smem_u32(&Bs[s][lr][(lc + 1) * 4]),                              \
                BT + (size_t)(col0 + lr) * K + (kt) * 32 + (lc + 1) * 8);        \
        cpa_commit();                                                            \
    } while (0)

    LOAD_STAGE(0, 0);
    LOAD_STAGE(1, 1);

    const int nk = K / 32;
    for (int kt = 0; kt < nk; ++kt) {
        const int s = kt & 1;
        cpa_wait<1>();
        __syncthreads();
#pragma unroll
        for (int kb = 0; kb < 16; kb += 8) {
            uint32_t af[4][4];
#pragma unroll
            for (int mt = 0; mt < 4; mt++) {
                int r = wm * 64 + mt * 16 + g;
                af[mt][0] = As[s][r][kb + t];     af[mt][1] = As[s][r + 8][kb + t];
                af[mt][2] = As[s][r][kb + t + 4]; af[mt][3] = As[s][r + 8][kb + t + 4];
            }
#pragma unroll
            for (int nt = 0; nt < 4; nt++) {
                int n = wn * 32 + nt * 8 + g;
                uint32_t bf[2];
                bf[0] = Bs[s][n][kb + t];
                bf[1] = Bs[s][n][kb + t + 4];
#pragma unroll
                for (int mt = 0; mt < 4; mt++)
                    mma_bf16(acc[mt][nt], af[mt], bf);
            }
        }
        __syncthreads();
        if (kt + 2 < nk) LOAD_STAGE(s, kt + 2);
    }
#undef LOAD_STAGE

#pragma unroll
    for (int mt = 0; mt < 4; mt++) {
        int row_lo = row0 + wm * 64 + mt * 16 + g;
        int row_hi = row_lo + 8;
#pragma unroll
        for (int nt = 0; nt < 4; nt++) {
            int col = col0 + wn * 32 + nt * 8 + t * 2;
            float v0 = acc[mt][nt][0], v1 = acc[mt][nt][1];
            float v2 = acc[mt][nt][2], v3 = acc[mt][nt][3];
            const float* blo = bias + (size_t)(row_lo & (Bn - 1)) * HIDd + col;
            const float* bhi = bias + (size_t)(row_hi & (Bn - 1)) * HIDd + col;
            v0 = fast_tanh(v0 + blo[0]); v1 = fast_tanh(v1 + blo[1]);
            v2 = fast_tanh(v2 + bhi[0]); v3 = fast_tanh(v3 + bhi[1]);
            *(uint32_t*)(Cout + (size_t)row_lo * N + col) = pack_bf16x2(v0, v1);
            *(uint32_t*)(Cout + (size_t)row_hi * N + col) = pack_bf16x2(v2, v3);
        }
    }
}

// ============ fused MLP2 + head: A2 = tanh(A1@W1T'+b1) in smem; P = A2@W2T'; ll
// 512 threads, 128 rows/block. smem (u32 words):
//   A1S [0, 33280)      resident A1 tile [128][260]
//   W1S [33280, 38400)  W1T stream [2][128][20]
//   A2S [38400, 47104)  A2 chunk   [128][68]
//   W2S [47104, 49152)  W2T chunk  [32][68]
//   PS  [49152, 53376)  P [128][33] fp32
//   B2S [53376, 53408)  b2 [32] fp32
// total 53408 u32 = 213632 B
__global__ __launch_bounds__(512, 1)
void mlp2h(const __nv_bfloat16* __restrict__ A1,
           const __nv_bfloat16* __restrict__ W1T,
           const float* __restrict__ b1,
           const __nv_bfloat16* __restrict__ W2T,
           const float* __restrict__ b2,
           const float* __restrict__ z)
{
    extern __shared__ uint32_t sm[];
    const uint32_t A1S = 0, W1S = 33280, A2S = 38400, W2S = 47104, PS = 49152, B2S = 53376;
    float* P   = (float*)(sm + PS);
    float* b2s = (float*)(sm + B2S);
    const int tid  = threadIdx.x;
    const int wid  = tid >> 5;          // 0..15
    const int lane = tid & 31;
    const int g    = lane >> 2;
    const int t4   = lane & 3;
    const int wm   = wid >> 2;          // 0..3 : 32m (GEMM2)
    const int wn   = wid & 3;           // 0..3 : 32n (GEMM2)
    const int wm3  = wid >> 1;          // 0..7 : 16m (GEMM3)
    const int wn3  = wid & 1;           // 0..1 : 16n (GEMM3)
    const int row0 = blockIdx.x * 128;
    uint32_t su = smem_u32(sm);

    // resident A1 tile: 8192 16B chunks
    {
        const __nv_bfloat16* Ag = A1 + (size_t)row0 * 512;
        for (int i = tid; i < 8192; i += 512) {
            int r = i >> 6, k16 = i & 63;
            cpa16_u(su + (A1S + (uint32_t)r * 260u + (uint32_t)k16 * 4u) * 4u,
                    Ag + (size_t)r * 512 + k16 * 8);
        }
        cpa_commit();
    }
    if (tid < 32) b2s[tid] = (tid < 30) ? b2[tid] : 0.f;

    float acc3[2][4];
#pragma unroll
    for (int nt = 0; nt < 2; nt++)
#pragma unroll
        for (int r = 0; r < 4; r++) acc3[nt][r] = 0.f;

    const int lrW = tid >> 2;           // 0..127
    const int lcW = (tid & 3) * 4;      // u32 0,4,8,12

#define LOADW(s, nb, kt)                                                         \
    do {                                                                         \
        cpa16_u(su + (W1S + (uint32_t)(s) * 2560u + (uint32_t)lrW * 20u + lcW) * 4u, \
                W1T + (size_t)((nb) * 128 + lrW) * 512 + (kt) * 32 + lcW * 2);   \
        cpa_commit();                                                            \
    } while (0)

    for (int nb = 0; nb < 4; nb++) {
        float acc2[2][4][4];
#pragma unroll
        for (int mt = 0; mt < 2; mt++)
#pragma unroll
            for (int nt = 0; nt < 4; nt++)
#pragma unroll
                for (int r = 0; r < 4; r++) acc2[mt][nt][r] = 0.f;

        LOADW(0, nb, 0);
        LOADW(1, nb, 1);

        for (int kt = 0; kt < 16; ++kt) {
            const int s = kt & 1;
            if (kt < 14) cpa_wait<1>(); else cpa_wait<0>();
            __syncthreads();
#pragma unroll
            for (int kb = 0; kb < 16; kb += 8) {
                uint32_t af[2][4];
#pragma unroll
                for (int mt = 0; mt < 2; mt++) {
                    uint32_t base = A1S + (uint32_t)(wm * 32 + mt * 16 + g) * 260u
                                  + (uint32_t)kt * 16u + kb + t4;
                    af[mt][0] = sm[base];        af[mt][1] = sm[base + 2080];   // +8*260
                    af[mt][2] = sm[base + 4];    af[mt][3] = sm[base + 2084];
                }
#pragma unroll
                for (int nt = 0; nt < 4; nt++) {
                    uint32_t bbase = W1S + (uint32_t)s * 2560u
                                   + (uint32_t)(wn * 32 + nt * 8 + g) * 20u + kb + t4;
                    uint32_t bf[2];
                    bf[0] = sm[bbase];
                    bf[1] = sm[bbase + 4];
#pragma unroll
                    for (int mt = 0; mt < 2; mt++)
                        mma_bf16(acc2[mt][nt], af[mt], bf);
                }
            }
            __syncthreads();
            if (kt + 2 < 16) LOADW(s, nb, kt + 2);
        }

        // epilogue GEMM2 chunk -> A2s (bf16), and load W2T chunk
#pragma unroll
        for (int mt = 0; mt < 2; mt++) {
            int row_lo = wm * 32 + mt * 16 + g;
            int row_hi = row_lo + 8;
#pragma unroll
            for (int nt = 0; nt < 4; nt++) {
                int colL = wn * 32 + nt * 8 + t4 * 2;
                int colG = nb * 128 + colL;
                float bb0 = b1[colG], bb1 = b1[colG + 1];
                float v0 = fast_tanh(acc2[mt][nt][0] + bb0);
                float v1 = fast_tanh(acc2[mt][nt][1] + bb1);
                float v2 = fast_tanh(acc2[mt][nt][2] + bb0);
                float v3 = fast_tanh(acc2[mt][nt][3] + bb1);
                sm[A2S + (uint32_t)row_lo * 68u + (colL >> 1)] = pack_bf16x2(v0, v1);
                sm[A2S + (uint32_t)row_hi * 68u + (colL >> 1)] = pack_bf16x2(v2, v3);
            }
        }
        {
            int r = tid >> 4, c4 = (tid & 15) * 4;
            cpa16_u(su + (W2S + (uint32_t)r * 68u + c4) * 4u,
                    W2T + (size_t)r * 512 + nb * 128 + (tid & 15) * 8);
            cpa_commit();
        }
        cpa_wait<0>();
        __syncthreads();   // A2s writes visible + W2T chunk ready

        // GEMM3: accumulate P over this chunk's K=128
#pragma unroll
        for (int s3 = 0; s3 < 8; s3++) {
            uint32_t af[4];
            {
                uint32_t base = A2S + (uint32_t)(wm3 * 16 + g) * 68u + s3 * 8 + t4;
                af[0] = sm[base];       af[1] = sm[base + 544];    // +8*68
                af[2] = sm[base + 4];   af[3] = sm[base + 548];
            }
#pragma unroll
            for (int nt = 0; nt < 2; nt++) {
                uint32_t bb = W2S + (uint32_t)(wn3 * 16 + nt * 8 + g) * 68u + s3 * 8 + t4;
                uint32_t bf[2];
                bf[0] = sm[bb];
                bf[1] = sm[bb + 4];
                mma_bf16(acc3[nt], af, bf);
            }
        }
        __syncthreads();   // free A2s / W2Ts for next chunk
    }
#undef LOADW

    // write P
    {
        int r_lo = wm3 * 16 + g;
        int r_hi = r_lo + 8;
#pragma unroll
        for (int nt = 0; nt < 2; nt++) {
            int c = wn3 * 16 + nt * 8 + t4 * 2;
            P[r_lo * 33 + c]     = acc3[nt][0];
            P[r_lo * 33 + c + 1] = acc3[nt][1];
            P[r_hi * 33 + c]     = acc3[nt][2];
            P[r_hi * 33 + c + 1] = acc3[nt][3];
        }
    }
    __syncthreads();

    if (tid < 128) {
        size_t r = (size_t)row0 + tid;
        int t = (int)(r >> 12);
        int b = (int)(r & 4095);
        float zv = z[(size_t)b * Dd + t];
        const float* p = P + tid * 33;
        float m1 = -1e30f, m2 = -1e30f;
        float term[10], lg[10];
#pragma unroll
        for (int k = 0; k < 10; k++) {
            float l  = p[k]      + b2s[k];
            float mu = p[10 + k] + b2s[10 + k];
            float ls = p[20 + k] + b2s[20 + k];
            float d = (zv - mu) * expf(-ls);
            float tv = l - ls - 0.91893853320467274f - 0.5f * d * d;
            term[k] = tv; lg[k] = l;
            m1 = fmaxf(m1, tv);
            m2 = fmaxf(m2, l);
        }
        float s1 = 0.f, s2 = 0.f;
#pragma unroll
        for (int k = 0; k < 10; k++) {
            s1 += expf(term[k] - m1);
            s2 += expf(lg[k] - m2);
        }
        g_ll[(size_t)t * Bn + b] = (m1 + logf(s1)) - (m2 + logf(s2));
    }
}

// ---------------- final: sort query desc (bitonic) + masked dot -------------
__global__ __launch_bounds__(128)
void final_kernel(const float* __restrict__ bb, const float* __restrict__ m,
                  float* __restrict__ out)
{
    __shared__ float s[128];
    __shared__ float red[128];
    int b = blockIdx.x, t = threadIdx.x;

    float q = -1.0f;
    if (t < Dd) {
        float bv = bb[(size_t)b * Dd + t];
        q = m[(size_t)b * Dd + t] * (1.0f - bv);
    }
    s[t] = q;
    __syncthreads();

    for (int k = 2; k <= 128; k <<= 1) {
        for (int j = k >> 1; j > 0; j >>= 1) {
            int ixj = t ^ j;
            if (ixj > t) {
                float a = s[t], c = s[ixj];
                bool up = ((t & k) == 0);
                if (up ? (a > c) : (a < c)) { s[t] = c; s[ixj] = a; }
            }
            __syncthreads();
        }
    }

    float prod = 0.f;
    if (t < Dd) prod = g_ll[(size_t)t * Bn + b] * s[127 - t];
    red[t] = prod;
    __syncthreads();
    for (int st = 64; st > 0; st >>= 1) {
        if (t < st) red[t] += red[t + st];
        __syncthreads();
    }
    if (t == 0) out[b] = red[0];
}

// ---------------- launch ----------------------------------------------------
extern "C" void kernel_launch(void* const* d_in, const int* in_sizes, int n_in,
                              void* d_out, int out_size)
{
    const float* z   = (const float*)d_in[0];
    const float* c   = (const float*)d_in[1];
    const float* bb  = (const float*)d_in[2];
    const float* m   = (const float*)d_in[3];
    const float* Wih = (const float*)d_in[4];
    const float* Whh = (const float*)d_in[5];
    const float* bih = (const float*)d_in[6];
    const float* bhh = (const float*)d_in[7];
    const float* W0  = (const float*)d_in[8];
    const float* b0  = (const float*)d_in[9];
    const float* W1  = (const float*)d_in[10];
    const float* b1  = (const float*)d_in[11];
    const float* W2  = (const float*)d_in[12];
    const float* b2  = (const float*)d_in[13];
    float* out = (float*)d_out;

    float *pConst, *pGic, *pMlpc, *pHf;
    __nv_bfloat16 *pHbf, *pWhhT, *pW0T, *pW1T, *pW2T, *pA1bf;
    cudaGetSymbolAddress((void**)&pConst, g_const);
    cudaGetSymbolAddress((void**)&pGic,   g_gic);
    cudaGetSymbolAddress((void**)&pMlpc,  g_mlpc);
    cudaGetSymbolAddress((void**)&pHf,    g_Hf);
    cudaGetSymbolAddress((void**)&pHbf,   g_Hbf);
    cudaGetSymbolAddress((void**)&pWhhT,  g_WhhT);
    cudaGetSymbolAddress((void**)&pW0T,   g_W0T);
    cudaGetSymbolAddress((void**)&pW1T,   g_W1T);
    cudaGetSymbolAddress((void**)&pW2T,   g_W2T);
    cudaGetSymbolAddress((void**)&pA1bf,  g_A1bf);

    static int attr_done = 0;
    if (!attr_done) {
        cudaFuncSetAttribute(gru_persist, cudaFuncAttributeMaxDynamicSharedMemorySize, 230400);
        cudaFuncSetAttribute(mlp2h, cudaFuncAttributeMaxDynamicSharedMemorySize, 213632);
        attr_done = 1;
    }

    // 0: merged prep
    {
        size_t tot = (size_t)Bn * CN + (size_t)Bn * Hh + Hh;
        prep_kernel<<<(unsigned)((tot + 255) / 256), 256>>>(c, bb, m, Wih);
    }
    // 1: transpose+convert Whh / W0[:H] / W1, and W2
    convT3_kernel<<<dim3(48, 16, 3), dim3(32, 8)>>>(Whh, W0, W1);
    w2t_kernel<<<64, 256>>>(W2);
    // 2: gi_const = const @ Wih[1:] + bih
    tgemm_kernel<<<dim3(G3 / 128, Bn / 128), 256>>>(pConst, Wih + G3, bih, pGic,
                                                    Bn, G3, CN);
    // 3: mlp_const = const @ W0[H:] + b0
    tgemm_kernel<<<dim3(HIDd / 128, Bn / 128), 256>>>(pConst, W0 + (size_t)Hh * HIDd,
                                                      b0, pMlpc, Bn, HIDd, CN);
    // 4: pack gic4
    gic4_pack_kernel<<<(Bn * Hh) / 256, 256>>>(bhh);
    // 5: recurrence — ONE persistent launch, 1024 threads
    gru_persist<<<NCTA, 1024, 230400>>>(pHbf, pHf, pWhhT, z);
    // 6: MLP layer 1
    bgemm_mlp<<<dim3(HIDd / 128, TOTR / 128), 256>>>(pHbf + (size_t)Bn * Hh, pW0T,
                                                     pMlpc, pA1bf, TOTR);
    // 7: fused MLP layer 2 + head + mixture
    mlp2h<<<TOTR / 128, 512, 213632>>>(pA1bf, pW1T, b1, pW2T, b2, z);
    // 8: final
    final_kernel<<<Bn, 128>>>(bb, m, out);
}

// round 16
// speedup vs baseline: 1.0474x; 1.0474x over previous
#include <cuda_runtime.h>
#include <cuda_bf16.h>
#include <math.h>
#include <stdint.h>

#define Bn   4096
#define Dd   112
#define NTd  200
#define Hh   512
#define HIDd 512
#define CN   536
#define G3   1536
#define TOTR (Dd*Bn)
#define NCTA 128

// ---------------- device scratch ---------------------------------------------
__device__ float g_const[(size_t)Bn * CN];
__device__ float g_gic  [(size_t)Bn * G3];
__device__ float4 g_gic4[(size_t)Bn * Hh];
__device__ float4 g_wz4 [Hh];
__device__ float g_mlpc [(size_t)Bn * HIDd];
__device__ float g_Hf   [2 * (size_t)Bn * Hh];
__device__ __nv_bfloat16 g_Hbf [(size_t)(Dd+1) * Bn * Hh];
__device__ __nv_bfloat16 g_WhhT[(size_t)G3 * Hh];
__device__ __nv_bfloat16 g_W0T [(size_t)HIDd * Hh];
__device__ __nv_bfloat16 g_W1T [(size_t)HIDd * HIDd];
__device__ __nv_bfloat16 g_W2T [(size_t)32 * 512];
__device__ __nv_bfloat16 g_A1bf[(size_t)TOTR * HIDd];
__device__ __nv_bfloat16 g_A2bf[(size_t)TOTR * HIDd];
__device__ float g_ll   [(size_t)Dd * Bn];           // [t][b]
__device__ unsigned g_bar_cnt2 [16];
__device__ unsigned g_bar_flag2[16];

// ---------------- helpers ----------------------------------------------------
__device__ __forceinline__ float fast_sig(float x)  { return 1.f / (1.f + __expf(-x)); }
__device__ __forceinline__ float fast_tanh(float x) { return fmaf(2.f, 1.f / (1.f + __expf(-2.f * x)), -1.f); }

__device__ __forceinline__ uint32_t pack_bf16x2(float lo, float hi)
{
    uint32_t r;
    asm("cvt.rn.bf16x2.f32 %0, %1, %2;" : "=r"(r) : "f"(hi), "f"(lo));
    return r;
}
__device__ __forceinline__ uint32_t smem_u32(const void* p)
{
    uint32_t a;
    asm("{ .reg .u64 t; cvta.to.shared.u64 t, %1; cvt.u32.u64 %0, t; }" : "=r"(a) : "l"(p));
    return a;
}
__device__ __forceinline__ void cpa16_u(uint32_t dst, const void* src)
{
    asm volatile("cp.async.cg.shared.global [%0], [%1], 16;\n" :: "r"(dst), "l"(src));
}
__device__ __forceinline__ void cpa8_u(uint32_t dst, const void* src)
{
    asm volatile("cp.async.ca.shared.global [%0], [%1], 8;\n" :: "r"(dst), "l"(src));
}
__device__ __forceinline__ void cpa_commit() { asm volatile("cp.async.commit_group;\n"); }
template<int N>
__device__ __forceinline__ void cpa_wait()   { asm volatile("cp.async.wait_group %0;\n" :: "n"(N)); }

__device__ __forceinline__ void ldsm_x4(uint32_t* r, uint32_t addr)
{
    asm volatile("ldmatrix.sync.aligned.m8n8.x4.shared.b16 {%0,%1,%2,%3}, [%4];"
        : "=r"(r[0]), "=r"(r[1]), "=r"(r[2]), "=r"(r[3]) : "r"(addr));
}

__device__ __forceinline__ uint32_t f2tf32(float x)
{
    uint32_t u;
    asm("cvt.rna.tf32.f32 %0, %1;" : "=r"(u) : "f"(x));
    return u;
}
__device__ __forceinline__ void mma_tf32(float* d, const uint32_t* a, const uint32_t* b)
{
    asm volatile(
        "mma.sync.aligned.m16n8k8.row.col.f32.tf32.tf32.f32 "
        "{%0,%1,%2,%3}, {%4,%5,%6,%7}, {%8,%9}, {%0,%1,%2,%3};\n"
        : "+f"(d[0]), "+f"(d[1]), "+f"(d[2]), "+f"(d[3])
        : "r"(a[0]), "r"(a[1]), "r"(a[2]), "r"(a[3]), "r"(b[0]), "r"(b[1]));
}
__device__ __forceinline__ void mma_bf16(float* d, const uint32_t* a, const uint32_t* b)
{
    asm volatile(
        "mma.sync.aligned.m16n8k16.row.col.f32.bf16.bf16.f32 "
        "{%0,%1,%2,%3}, {%4,%5,%6,%7}, {%8,%9}, {%0,%1,%2,%3};\n"
        : "+f"(d[0]), "+f"(d[1]), "+f"(d[2]), "+f"(d[3])
        : "r"(a[0]), "r"(a[1]), "r"(a[2]), "r"(a[3]), "r"(b[0]), "r"(b[1]));
}

// ---------------- merged prep kernel -----------------------------------------
__global__ void prep_kernel(const float* __restrict__ c,
                            const float* __restrict__ bb,
                            const float* __restrict__ m,
                            const float* __restrict__ Wih)
{
    size_t idx = (size_t)blockIdx.x * blockDim.x + threadIdx.x;
    const size_t R1 = (size_t)Bn * CN;
    const size_t R2 = R1 + (size_t)Bn * Hh;
    if (idx < R1) {
        int b = (int)(idx / CN);
        int i = (int)(idx % CN);
        float v;
        if (i < Dd + NTd)            v = c [(size_t)b * (Dd + NTd) + i];
        else if (i < Dd + NTd + Dd)  v = bb[(size_t)b * Dd + (i - (Dd + NTd))];
        else                         v = m [(size_t)b * Dd + (i - (Dd + NTd + Dd))];
        g_const[idx] = v;
    } else if (idx < R2) {
        size_t i2 = idx - R1;
        g_Hf[i2] = 0.f;
        g_Hbf[i2] = __float2bfloat16(0.f);
    } else if (idx < R2 + Hh) {
        int j = (int)(idx - R2);
        g_wz4[j] = make_float4(Wih[j], Wih[512 + j], Wih[1024 + j], 0.f);
        if (j < 16) { g_bar_cnt2[j] = 0; g_bar_flag2[j] = 0; }
    }
}

__global__ void gic4_pack_kernel(const float* __restrict__ bhh)
{
    size_t idx = (size_t)blockIdx.x * blockDim.x + threadIdx.x;
    if (idx >= (size_t)Bn * Hh) return;
    int b = (int)(idx >> 9);
    int j = (int)(idx & 511);
    const float* g = g_gic + (size_t)b * G3;
    g_gic4[idx] = make_float4(g[j] + bhh[j],
                              g[512 + j] + bhh[512 + j],
                              g[1024 + j],
                              bhh[1024 + j]);
}

__global__ void convT3_kernel(const float* __restrict__ Whh,
                              const float* __restrict__ W0,
                              const float* __restrict__ W1)
{
    __shared__ float tile[32][33];
    const float* in;
    __nv_bfloat16* out;
    int Krows = 512, Ncols;
    if (blockIdx.z == 0)      { in = Whh; out = g_WhhT; Ncols = G3; }
    else if (blockIdx.z == 1) { in = W0;  out = g_W0T;  Ncols = HIDd; }
    else                      { in = W1;  out = g_W1T;  Ncols = HIDd; }
    int n0 = blockIdx.x * 32;
    if (n0 >= Ncols) return;
    int k0 = blockIdx.y * 32;
    int tx = threadIdx.x, ty = threadIdx.y;
    for (int i = ty; i < 32; i += 8)
        tile[i][tx] = in[(size_t)(k0 + i) * Ncols + n0 + tx];
    __syncthreads();
    for (int i = ty; i < 32; i += 8)
        out[(size_t)(n0 + i) * Krows + k0 + tx] = __float2bfloat16(tile[tx][i]);
}

__global__ void w2t_kernel(const float* __restrict__ W2)
{
    int idx = blockIdx.x * 256 + threadIdx.x;
    if (idx >= 32 * 512) return;
    int n = idx >> 9, k = idx & 511;
    g_W2T[idx] = (n < 30) ? __float2bfloat16(W2[k * 30 + n]) : __float2bfloat16(0.f);
}

// ---------------- tf32 GEMM for K=536 precompute -----------------------------
__global__ __launch_bounds__(256)
void tgemm_kernel(const float* __restrict__ A, const float* __restrict__ B,
                  const float* __restrict__ bias, float* __restrict__ C,
                  int M, int N, int K)
{
    __shared__ uint32_t As[128][12];
    __shared__ uint32_t Bs[8][136];

    const int tid  = threadIdx.x;
    const int wid  = tid >> 5;
    const int lane = tid & 31;
    const int gid  = lane >> 2;
    const int tig  = lane & 3;
    const int wm   = wid >> 2;
    const int wn   = wid & 3;
    const int row0 = blockIdx.y * 128;
    const int col0 = blockIdx.x * 128;

    float acc[4][4][4];
#pragma unroll
    for (int mt = 0; mt < 4; mt++)
#pragma unroll
        for (int nt = 0; nt < 4; nt++)
#pragma unroll
            for (int r = 0; r < 4; r++) acc[mt][nt][r] = 0.f;

    const int ar = tid >> 1;
    const int ak = (tid & 1) * 4;
    const int bk = tid >> 5;
    const int bn = (tid & 31) * 4;
    const int niter = K >> 3;

    const float* Ag = A + (size_t)(row0 + ar) * K + ak;
    const float* Bg = B + (size_t)bk * N + col0 + bn;

    float4 pa = *(const float4*)Ag;
    float4 pb = *(const float4*)Bg;

    for (int it = 0; it < niter; ++it) {
        As[ar][ak + 0] = f2tf32(pa.x); As[ar][ak + 1] = f2tf32(pa.y);
        As[ar][ak + 2] = f2tf32(pa.z); As[ar][ak + 3] = f2tf32(pa.w);
        Bs[bk][bn + 0] = f2tf32(pb.x); Bs[bk][bn + 1] = f2tf32(pb.y);
        Bs[bk][bn + 2] = f2tf32(pb.z); Bs[bk][bn + 3] = f2tf32(pb.w);
        __syncthreads();
        if (it + 1 < niter) {
            pa = *(const float4*)(Ag + (size_t)(it + 1) * 8);
            pb = *(const float4*)(Bg + (size_t)(it + 1) * 8 * N);
        }
        uint32_t af[4][4];
#pragma unroll
        for (int mt = 0; mt < 4; mt++) {
            int rb = wm * 64 + mt * 16 + gid;
            af[mt][0] = As[rb][tig];     af[mt][1] = As[rb + 8][tig];
            af[mt][2] = As[rb][tig + 4]; af[mt][3] = As[rb + 8][tig + 4];
        }
        uint32_t bf[4][2];
#pragma unroll
        for (int nt = 0; nt < 4; nt++) {
            int cb = wn * 32 + nt * 8 + gid;
            bf[nt][0] = Bs[tig][cb]; bf[nt][1] = Bs[tig + 4][cb];
        }
#pragma unroll
        for (int mt = 0; mt < 4; mt++)
#pragma unroll
            for (int nt = 0; nt < 4; nt++)
                mma_tf32(acc[mt][nt], af[mt], bf[nt]);
        __syncthreads();
    }
#pragma unroll
    for (int mt = 0; mt < 4; mt++) {
        int row_lo = row0 + wm * 64 + mt * 16 + gid;
        int row_hi = row_lo + 8;
#pragma unroll
        for (int nt = 0; nt < 4; nt++) {
            int col = col0 + wn * 32 + nt * 8 + tig * 2;
            float b0 = bias[col], b1 = bias[col + 1];
            *(float2*)(C + (size_t)row_lo * N + col) =
                make_float2(acc[mt][nt][0] + b0, acc[mt][nt][1] + b1);
            *(float2*)(C + (size_t)row_hi * N + col) =
                make_float2(acc[mt][nt][2] + b0, acc[mt][nt][3] + b1);
        }
    }
}

// ============ PERSISTENT weight-stationary GRU recurrence (1024 thr) =========
// Inner loop uses ldmatrix.x4 (A) + 3x ldmatrix.x4 (B gates), bit-identical
// fragments to the previous scalar LDS version.
__global__ __launch_bounds__(1024, 1)
void gru_persist(const __nv_bfloat16* __restrict__ Hbf,
                 float* __restrict__ Hf,
                 const __nv_bfloat16* __restrict__ WhhT,
                 const float* __restrict__ z)
{
    extern __shared__ uint32_t sm[];
    const int tid  = threadIdx.x;
    const int wid  = tid >> 5;
    const int lane = tid & 31;
    const int gid  = lane >> 2;
    const int t4   = lane & 3;
    const int wm   = wid >> 2;
    const int wn   = wid & 3;
    const int jb   = blockIdx.x & 7;
    const int mb   = blockIdx.x >> 3;
    uint32_t su = smem_u32(sm);
    const uint32_t BW = 7680;

    for (int i = tid; i < 12288; i += 1024) {
        int n_row = i >> 6;
        int c16   = i & 63;
        int g = n_row >> 6, n = n_row & 63;
        cpa16_u(su + (BW + (uint32_t)n_row * 260u + (uint32_t)c16 * 4u) * 4u,
                WhhT + ((size_t)(g * 512 + jb * 64 + n)) * 512 + c16 * 8);
    }
    cpa_commit(); cpa_wait<0>(); __syncthreads();

    const int ar  = tid >> 3;
    const int ac4 = (tid & 7) << 1;

    // ldmatrix per-lane bases (u32-word units)
    const int lrow8 = (lane & 7) + ((lane >> 3) & 1) * 8;   // tile row select
    const int khalf = (lane >> 4) * 4;                      // k8-half select
    const uint32_t aBase = (uint32_t)(wm * 16 + lrow8) * 20u + khalf;
    uint32_t bBase[3];
#pragma unroll
    for (int g = 0; g < 3; g++)
        bBase[g] = BW + (uint32_t)(g * 64 + wn * 16 + lrow8) * 260u + khalf;

#define LOADA(s, kc)                                                            \
    do {                                                                        \
        cpa8_u(su + ((uint32_t)(s) * 2560u + (uint32_t)ar * 20u + ac4) * 4u,    \
               Ag + (size_t)ar * 512 + (kc) * 32 + ac4 * 2);                    \
        cpa_commit();                                                           \
    } while (0)

    for (int t = 0; t < Dd; t++) {
        const __nv_bfloat16* Abase = Hbf + (size_t)t * Bn * Hh + (size_t)mb * 256 * 512;
        const float* Hfp = Hf + (size_t)(t & 1) * Bn * Hh;
        float* Hfn       = Hf + (size_t)((t + 1) & 1) * Bn * Hh;
        __nv_bfloat16* Hbn = (__nv_bfloat16*)(Hbf + (size_t)(t + 1) * Bn * Hh);

        for (int mh = 0; mh < 2; mh++) {
            const __nv_bfloat16* Ag = Abase + (size_t)mh * 128 * 512;

            float acc[3][2][4];
#pragma unroll
            for (int g = 0; g < 3; g++)
#pragma unroll
                for (int nt = 0; nt < 2; nt++)
#pragma unroll
                    for (int r = 0; r < 4; r++) acc[g][nt][r] = 0.f;

            LOADA(0, 0);
            LOADA(1, 1);

            for (int kc = 0; kc < 16; kc++) {
                const int s = kc % 3;
                if (kc < 14) cpa_wait<1>(); else cpa_wait<0>();
                __syncthreads();
                if (kc + 2 < 16) LOADA((kc + 2) % 3, kc + 2);

#pragma unroll
                for (int kb = 0; kb < 16; kb += 8) {
                    uint32_t af[4];
                    ldsm_x4(af, su + 4u * ((uint32_t)s * 2560u + aBase + kb));
#pragma unroll
                    for (int g = 0; g < 3; g++) {
                        uint32_t bq[4];
                        ldsm_x4(bq, su + 4u * (bBase[g] + (uint32_t)kc * 16u + kb));
                        uint32_t b0[2] = { bq[0], bq[2] };
                        uint32_t b1[2] = { bq[1], bq[3] };
                        mma_bf16(acc[g][0], af, b0);
                        mma_bf16(acc[g][1], af, b1);
                    }
                }
            }

            {
                int b_lo = mb * 256 + mh * 128 + wm * 16 + gid;
                int b_hi = b_lo + 8;
                float zt_lo = (t == 0) ? -1.0f : z[(size_t)b_lo * Dd + (t - 1)];
                float zt_hi = (t == 0) ? -1.0f : z[(size_t)b_hi * Dd + (t - 1)];
                const float4* g4lo = g_gic4 + (size_t)b_lo * Hh;
                const float4* g4hi = g_gic4 + (size_t)b_hi * Hh;
                const float* hp_lo = Hfp + (size_t)b_lo * Hh;
                const float* hp_hi = Hfp + (size_t)b_hi * Hh;
                float* hf_lo = Hfn + (size_t)b_lo * Hh;
                float* hf_hi = Hfn + (size_t)b_hi * Hh;
                __nv_bfloat16* hb_lo = Hbn + (size_t)b_lo * Hh;
                __nv_bfloat16* hb_hi = Hbn + (size_t)b_hi * Hh;

#pragma unroll
                for (int nt = 0; nt < 2; nt++) {
                    int jc = jb * 64 + wn * 16 + nt * 8 + t4 * 2;
                    float hlo[2], hhi[2];
#pragma unroll
                    for (int cc = 0; cc < 2; cc++) {
                        int j = jc + cc;
                        float4 w4  = g_wz4[j];
                        float4 glo = g4lo[j];
                        float4 ghi = g4hi[j];
                        {
                            float r = fast_sig(fmaf(zt_lo, w4.x, glo.x) + acc[0][nt][cc]);
                            float u = fast_sig(fmaf(zt_lo, w4.y, glo.y) + acc[1][nt][cc]);
                            float n = fast_tanh(fmaf(r, acc[2][nt][cc] + glo.w,
                                                     fmaf(zt_lo, w4.z, glo.z)));
                            hlo[cc] = fmaf(u, hp_lo[j] - n, n);
                        }
                        {
                            float r = fast_sig(fmaf(zt_hi, w4.x, ghi.x) + acc[0][nt][2 + cc]);
                            float u = fast_sig(fmaf(zt_hi, w4.y, ghi.y) + acc[1][nt][2 + cc]);
                            float n = fast_tanh(fmaf(r, acc[2][nt][2 + cc] + ghi.w,
                                                     fmaf(zt_hi, w4.z, ghi.z)));
                            hhi[cc] = fmaf(u, hp_hi[j] - n, n);
                        }
                    }
                    *(float2*)(hf_lo + jc) = make_float2(hlo[0], hlo[1]);
                    *(float2*)(hf_hi + jc) = make_float2(hhi[0], hhi[1]);
                    *(uint32_t*)(hb_lo + jc) = pack_bf16x2(hlo[0], hlo[1]);
                    *(uint32_t*)(hb_hi + jc) = pack_bf16x2(hhi[0], hhi[1]);
                }
            }
            __syncthreads();
        }

        __threadfence();
        __syncthreads();
        if (tid == 0) {
            unsigned v = atomicAdd(&g_bar_cnt2[mb], 1u);
            if (v == 7u) {
                g_bar_cnt2[mb] = 0;
                __threadfence();
                atomicExch(&g_bar_flag2[mb], (unsigned)(t + 1));
            } else {
                while (atomicAdd(&g_bar_flag2[mb], 0u) < (unsigned)(t + 1)) { }
            }
        }
        __syncthreads();
    }
#undef LOADA
}

// ============ bf16 MLP GEMM (A bf16 [M][512], BT bf16 [512][512]) ============
template<int MODE>
__global__ __launch_bounds__(256)
void bgemm_mlp(const __nv_bfloat16* __restrict__ A, const __nv_bfloat16* __restrict__ BT,
               const float* __restrict__ bias, __nv_bfloat16* __restrict__ Cout, int M)
{
    const int K = 512, N = 512;
    __shared__ uint32_t As[2][128][20];
    __shared__ uint32_t Bs[2][128][20];

    const int tid  = threadIdx.x;
    const int wid  = tid >> 5;
    const int lane = tid & 31;
    const int g    = lane >> 2;
    const int t    = lane & 3;
    const int wm   = wid >> 2;
    const int wn   = wid & 3;

    const int row0 = blockIdx.y * 128;
    const int col0 = blockIdx.x * 128;

    float acc[4][4][4];
#pragma unroll
    for (int mt = 0; mt < 4; mt++)
#pragma unroll
        for (int nt = 0; nt < 4; nt++)
#pragma unroll
            for (int r = 0; r < 4; r++) acc[mt][nt][r] = 0.f;

    const int lr = tid >> 1;
    const int lc = (tid & 1) * 2;

#define LOAD_STAGE(s, kt)                                                        \
    do {                                                                         \
        cpa16_u(smem_u32(&As[s][lr][lc * 4]),                                    \
                A  + (size_t)(row0 + lr) * K + (kt) * 32 + lc * 8);              \
        cpa16_u(smem_u32(&As[s][lr][(lc + 1) * 4]),                              \
                A  + (size_t)(row0 + lr) * K + (kt) * 32 + (lc + 1) * 8);        \
        cpa16_u(smem_u32(&Bs[s][lr][lc * 4]),                                    \
                BT + (size_t)(col0 + lr) * K + (kt) * 32 + lc * 8);              \
        cpa16_u(smem_u32(&Bs[s][lr][(lc + 1) * 4]),                              \
                BT + (size_t)(col0 + lr) * K + (kt) * 32 + (lc + 1) * 8);        \
        cpa_commit();                                                            \
    } while (0)

    LOAD_STAGE(0, 0);
    LOAD_STAGE(1, 1);

    const int nk = K / 32;
    for (int kt = 0; kt < nk; ++kt) {
        const int s = kt & 1;
        cpa_wait<1>();
        __syncthreads();
#pragma unroll
        for (int kb = 0; kb < 16; kb += 8) {
            uint32_t af[4][4];
#pragma unroll
            for (int mt = 0; mt < 4; mt++) {
                int r = wm * 64 + mt * 16 + g;
                af[mt][0] = As[s][r][kb + t];     af[mt][1] = As[s][r + 8][kb + t];
                af[mt][2] = As[s][r][kb + t + 4]; af[mt][3] = As[s][r + 8][kb + t + 4];
            }
#pragma unroll
            for (int nt = 0; nt < 4; nt++) {
                int n = wn * 32 + nt * 8 + g;
                uint32_t bf[2];
                bf[0] = Bs[s][n][kb + t];
                bf[1] = Bs[s][n][kb + t + 4];
#pragma unroll
                for (int mt = 0; mt < 4; mt++)
                    mma_bf16(acc[mt][nt], af[mt], bf);
            }
        }
        __syncthreads();
        if (kt + 2 < nk) LOAD_STAGE(s, kt + 2);
    }
#undef LOAD_STAGE

#pragma unroll
    for (int mt = 0; mt < 4; mt++) {
        int row_lo = row0 + wm * 64 + mt * 16 + g;
        int row_hi = row_lo + 8;
#pragma unroll
        for (int nt = 0; nt < 4; nt++) {
            int col = col0 + wn * 32 + nt * 8 + t * 2;
            float v0 = acc[mt][nt][0], v1 = acc[mt][nt][1];
            float v2 = acc[mt][nt][2], v3 = acc[mt][nt][3];
            if (MODE == 0) {
                const float* blo = bias + (size_t)(row_lo & (Bn - 1)) * HIDd + col;
                const float* bhi = bias + (size_t)(row_hi & (Bn - 1)) * HIDd + col;
                v0 = fast_tanh(v0 + blo[0]); v1 = fast_tanh(v1 + blo[1]);
                v2 = fast_tanh(v2 + bhi[0]); v3 = fast_tanh(v3 + bhi[1]);
            } else {
                float b0 = bias[col], b1 = bias[col + 1];
                v0 = fast_tanh(v0 + b0); v1 = fast_tanh(v1 + b1);
                v2 = fast_tanh(v2 + b0); v3 = fast_tanh(v3 + b1);
            }
            *(uint32_t*)(Cout + (size_t)row_lo * N + col) = pack_bf16x2(v0, v1);
            *(uint32_t*)(Cout + (size_t)row_hi * N + col) = pack_bf16x2(v2, v3);
        }
    }
}

// ============ mma-based head (triple-buffered A) =============================
__global__ __launch_bounds__(256, 2)
void head_mma(const __nv_bfloat16* __restrict__ A2,
              const __nv_bfloat16* __restrict__ W2T,
              const float* __restrict__ b2,
              const float* __restrict__ z)
{
    extern __shared__ uint32_t sm[];
    float* P   = (float*)(sm + 16000);
    float* b2s = (float*)(sm + 20224);
    const int tid  = threadIdx.x;
    const int wid  = tid >> 5;
    const int lane = tid & 31;
    const int g    = lane >> 2;
    const int t4   = lane & 3;
    const int row0 = blockIdx.x * 128;
    uint32_t su = smem_u32(sm);

    for (int i = tid; i < 8192; i += 256) {
        int n = i >> 8, k4 = i & 255;
        sm[7680 + n * 260 + k4] = ((const uint32_t*)W2T)[n * 256 + k4];
    }
    if (tid < 32) b2s[tid] = (tid < 30) ? b2[tid] : 0.f;

    const int lr = tid >> 1;
    const int lc = (tid & 1) * 2;
    const __nv_bfloat16* Ag = A2 + (size_t)row0 * 512;

#define HLOAD(s, kt)                                                            \
    do {                                                                        \
        cpa16_u(su + ((uint32_t)(s) * 2560u + (uint32_t)lr * 20u + lc * 4) * 4u,\
                Ag + (size_t)lr * 512 + (kt) * 32 + lc * 8);                    \
        cpa16_u(su + ((uint32_t)(s) * 2560u + (uint32_t)lr * 20u + (lc + 1) * 4) * 4u, \
                Ag + (size_t)lr * 512 + (kt) * 32 + (lc + 1) * 8);              \
        cpa_commit();                                                           \
    } while (0)

    float acc[4][4];
#pragma unroll
    for (int nt = 0; nt < 4; nt++)
#pragma unroll
        for (int r = 0; r < 4; r++) acc[nt][r] = 0.f;

    HLOAD(0, 0);
    HLOAD(1, 1);

    for (int kt = 0; kt < 16; ++kt) {
        const int s = kt % 3;
        if (kt < 14) cpa_wait<1>(); else cpa_wait<0>();
        __syncthreads();
        if (kt + 2 < 16) HLOAD((kt + 2) % 3, kt + 2);

#pragma unroll
        for (int kb = 0; kb < 16; kb += 8) {
            uint32_t af[4];
            {
                uint32_t base = (uint32_t)s * 2560u + (uint32_t)(wid * 16 + g) * 20u + kb + t4;
                af[0] = sm[base];       af[1] = sm[base + 160];
                af[2] = sm[base + 4];   af[3] = sm[base + 164];
            }
#pragma unroll
            for (int nt = 0; nt < 4; nt++) {
                int n = nt * 8 + g;
                uint32_t bbase = 7680 + (uint32_t)n * 260u + (uint32_t)kt * 16u + kb + t4;
                uint32_t bf[2];
                bf[0] = sm[bbase];
                bf[1] = sm[bbase + 4];
                mma_bf16(acc[nt], af, bf);
            }
        }
    }
#undef HLOAD

    __syncthreads();
    {
        int r_lo = wid * 16 + g;
        int r_hi = r_lo + 8;
#pragma unroll
        for (int nt = 0; nt < 4; nt++) {
            int cl = nt * 8 + t4 * 2;
            P[r_lo * 33 + cl]     = acc[nt][0];
            P[r_lo * 33 + cl + 1] = acc[nt][1];
            P[r_hi * 33 + cl]     = acc[nt][2];
            P[r_hi * 33 + cl + 1] = acc[nt][3];
        }
    }
    __syncthreads();

    if (tid < 128) {
        size_t r = (size_t)row0 + tid;
        int t = (int)(r >> 12);
        int b = (int)(r & 4095);
        float zv = z[(size_t)b * Dd + t];
        const float* p = P + tid * 33;
        float m1 = -1e30f, m2 = -1e30f;
        float term[10], lg[10];
#pragma unroll
        for (int k = 0; k < 10; k++) {
            float l  = p[k]      + b2s[k];
            float mu = p[10 + k] + b2s[10 + k];
            float ls = p[20 + k] + b2s[20 + k];
            float d = (zv - mu) * expf(-ls);
            float tv = l - ls - 0.91893853320467274f - 0.5f * d * d;
            term[k] = tv; lg[k] = l;
            m1 = fmaxf(m1, tv);
            m2 = fmaxf(m2, l);
        }
        float s1 = 0.f, s2 = 0.f;
#pragma unroll
        for (int k = 0; k < 10; k++) {
            s1 += expf(term[k] - m1);
            s2 += expf(lg[k] - m2);
        }
        g_ll[(size_t)t * Bn + b] = (m1 + logf(s1)) - (m2 + logf(s2));
    }
}

// ---------------- final: sort query desc (bitonic) + masked dot -------------
__global__ __launch_bounds__(128)
void final_kernel(const float* __restrict__ bb, const float* __restrict__ m,
                  float* __restrict__ out)
{
    __shared__ float s[128];
    __shared__ float red[128];
    int b = blockIdx.x, t = threadIdx.x;

    float q = -1.0f;
    if (t < Dd) {
        float bv = bb[(size_t)b * Dd + t];
        q = m[(size_t)b * Dd + t] * (1.0f - bv);
    }
    s[t] = q;
    __syncthreads();

    for (int k = 2; k <= 128; k <<= 1) {
        for (int j = k >> 1; j > 0; j >>= 1) {
            int ixj = t ^ j;
            if (ixj > t) {
                float a = s[t], c = s[ixj];
                bool up = ((t & k) == 0);
                if (up ? (a > c) : (a < c)) { s[t] = c; s[ixj] = a; }
            }
            __syncthreads();
        }
    }

    float prod = 0.f;
    if (t < Dd) prod = g_ll[(size_t)t * Bn + b] * s[127 - t];
    red[t] = prod;
    __syncthreads();
    for (int st = 64; st > 0; st >>= 1) {
        if (t < st) red[t] += red[t + st];
        __syncthreads();
    }
    if (t == 0) out[b] = red[0];
}

// ---------------- launch ----------------------------------------------------
extern "C" void kernel_launch(void* const* d_in, const int* in_sizes, int n_in,
                              void* d_out, int out_size)
{
    const float* z   = (const float*)d_in[0];
    const float* c   = (const float*)d_in[1];
    const float* bb  = (const float*)d_in[2];
    const float* m   = (const float*)d_in[3];
    const float* Wih = (const float*)d_in[4];
    const float* Whh = (const float*)d_in[5];
    const float* bih = (const float*)d_in[6];
    const float* bhh = (const float*)d_in[7];
    const float* W0  = (const float*)d_in[8];
    const float* b0  = (const float*)d_in[9];
    const float* W1  = (const float*)d_in[10];
    const float* b1  = (const float*)d_in[11];
    const float* W2  = (const float*)d_in[12];
    const float* b2  = (const float*)d_in[13];
    float* out = (float*)d_out;

    float *pConst, *pGic, *pMlpc, *pHf;
    __nv_bfloat16 *pHbf, *pWhhT, *pW0T, *pW1T, *pW2T, *pA1bf, *pA2bf;
    cudaGetSymbolAddress((void**)&pConst, g_const);
    cudaGetSymbolAddress((void**)&pGic,   g_gic);
    cudaGetSymbolAddress((void**)&pMlpc,  g_mlpc);
    cudaGetSymbolAddress((void**)&pHf,    g_Hf);
    cudaGetSymbolAddress((void**)&pHbf,   g_Hbf);
    cudaGetSymbolAddress((void**)&pWhhT,  g_WhhT);
    cudaGetSymbolAddress((void**)&pW0T,   g_W0T);
    cudaGetSymbolAddress((void**)&pW1T,   g_W1T);
    cudaGetSymbolAddress((void**)&pW2T,   g_W2T);
    cudaGetSymbolAddress((void**)&pA1bf,  g_A1bf);
    cudaGetSymbolAddress((void**)&pA2bf,  g_A2bf);

    static int attr_done = 0;
    if (!attr_done) {
        cudaFuncSetAttribute(gru_persist, cudaFuncAttributeMaxDynamicSharedMemorySize, 230400);
        cudaFuncSetAttribute(head_mma, cudaFuncAttributeMaxDynamicSharedMemorySize, 81024);
        attr_done = 1;
    }

    // 0: merged prep
    {
        size_t tot = (size_t)Bn * CN + (size_t)Bn * Hh + Hh;
        prep_kernel<<<(unsigned)((tot + 255) / 256), 256>>>(c, bb, m, Wih);
    }
    // 1: transpose+convert Whh / W0[:H] / W1, and W2
    convT3_kernel<<<dim3(48, 16, 3), dim3(32, 8)>>>(Whh, W0, W1);
    w2t_kernel<<<64, 256>>>(W2);
    // 2: gi_const = const @ Wih[1:] + bih
    tgemm_kernel<<<dim3(G3 / 128, Bn / 128), 256>>>(pConst, Wih + G3, bih, pGic,
                                                    Bn, G3, CN);
    // 3: mlp_const = const @ W0[H:] + b0
    tgemm_kernel<<<dim3(HIDd / 128, Bn / 128), 256>>>(pConst, W0 + (size_t)Hh * HIDd,
                                                      b0, pMlpc, Bn, HIDd, CN);
    // 4: pack gic4
    gic4_pack_kernel<<<(Bn * Hh) / 256, 256>>>(bhh);
    // 5: recurrence — ONE persistent launch, 1024 threads, ldmatrix fragments
    gru_persist<<<NCTA, 1024, 230400>>>(pHbf, pHf, pWhhT, z);
    // 6-7: batched MLP (bf16 out)
    bgemm_mlp<0><<<dim3(HIDd / 128, TOTR / 128), 256>>>(pHbf + (size_t)Bn * Hh, pW0T,
                                                        pMlpc, pA1bf, TOTR);
    bgemm_mlp<1><<<dim3(HIDd / 128, TOTR / 128), 256>>>(pA1bf, pW1T, b1, pA2bf, TOTR);
    // 8: mma head
    head_mma<<<TOTR / 128, 256, 81024>>>(pA2bf, pW2T, b2, z);
    // 9: final
    final_kernel<<<Bn, 128>>>(bb, m, out);
}